// round 1
// baseline (speedup 1.0000x reference)
#include <cuda_runtime.h>
#include <cuda_bf16.h>

// Problem constants
#define B_  32
#define T_  64
#define M_  (B_*T_)      // 2048
#define N_  16           // neighbors
#define E_  128
#define H_  128
#define G4_ 512          // 4*H
#define C_  100000
#define K_  256          // UE + H
#define NEG 0.01f

// ---------------- scratch (device globals; no runtime alloc) ----------------
__device__ __align__(16) float g_spwT[E_*E_];       // [e][f]
__device__ __align__(16) float g_tpwT[E_*E_];
__device__ __align__(16) float g_spaWT[2*E_*E_];    // [c][f], c in [0,256)
__device__ __align__(16) float g_tpaWT[2*E_*E_];
__device__ __align__(16) float g_WT [E_*G4_];       // [e][g]
__device__ __align__(16) float g_sWT[E_*G4_];
__device__ __align__(16) float g_tWT[E_*G4_];
__device__ __align__(16) float g_UT4[E_*G4_];       // [e][j][k] k=gate
__device__ __align__(16) float g_spatial[M_*E_];
__device__ __align__(16) float g_temporal[M_*E_];
__device__ __align__(16) float g_preXST[M_*G4_];
__device__ __align__(16) float g_hout[M_*H_];
__device__ __align__(16) float g_fused[M_*K_];

// ---------------- kernel 1: weight transposes ----------------
__global__ void prep_kernel(const float* __restrict__ sp_w, const float* __restrict__ sp_aW,
                            const float* __restrict__ tp_w, const float* __restrict__ tp_aW,
                            const float* __restrict__ W, const float* __restrict__ U,
                            const float* __restrict__ sW, const float* __restrict__ tW) {
    int i = blockIdx.x * blockDim.x + threadIdx.x;
    int stride = gridDim.x * blockDim.x;
    for (int j = i; j < E_*E_; j += stride) {
        int f = j >> 7, e = j & 127;
        g_spwT[e*E_ + f] = sp_w[j];
        g_tpwT[e*E_ + f] = tp_w[j];
    }
    for (int j = i; j < E_*2*E_; j += stride) {
        int f = j >> 8, c = j & 255;
        g_spaWT[c*E_ + f] = sp_aW[j];
        g_tpaWT[c*E_ + f] = tp_aW[j];
    }
    for (int j = i; j < G4_*E_; j += stride) {
        int g = j >> 7, e = j & 127;
        g_WT [e*G4_ + g] = W[j];
        g_sWT[e*G4_ + g] = sW[j];
        g_tWT[e*G4_ + g] = tW[j];
        int k = g >> 7, jj = g & 127;
        g_UT4[(e*H_ + jj)*4 + k] = U[j];
    }
}

// ---------------- kernel 2: GAT (spatial + temporal), one block per (b,t,which) --
__global__ void gat_kernel(const int* __restrict__ x,
                           const int* __restrict__ sp_neigh, const int* __restrict__ tp_neigh,
                           const float* __restrict__ poi,
                           const float* __restrict__ sp_ab, const float* __restrict__ tp_ab) {
    int m = blockIdx.x;
    int which = blockIdx.y;                 // 0 spatial, 1 temporal
    int f = threadIdx.x;                    // 0..127 feature
    const int*   neigh  = which ? tp_neigh : sp_neigh;
    const float* wT     = which ? g_tpwT   : g_spwT;
    const float* aWT    = which ? g_tpaWT  : g_spaWT;
    const float* ab     = which ? tp_ab    : sp_ab;
    float*       outbuf = which ? g_temporal : g_spatial;

    __shared__ float nb[17][E_];    // rows 0..15 neighbors, row 16 = x
    __shared__ float px[E_];
    __shared__ float pn[N_][E_];

    {
        int ix = x[m];
        nb[16][f] = poi[ix*E_ + f];
        #pragma unroll
        for (int n = 0; n < N_; n++) {
            int idx = neigh[m*N_ + n];
            nb[n][f] = poi[idx*E_ + f];
        }
    }
    __syncthreads();

    // projection: px[f], pn[n][f]
    float accx = 0.f;
    float accn[N_];
    #pragma unroll
    for (int n = 0; n < N_; n++) accn[n] = 0.f;
    for (int e = 0; e < E_; e++) {
        float wv = wT[e*E_ + f];
        accx += nb[16][e] * wv;
        #pragma unroll
        for (int n = 0; n < N_; n++) accn[n] += nb[n][e] * wv;
    }
    px[f] = accx;
    #pragma unroll
    for (int n = 0; n < N_; n++) pn[n][f] = accn[n];
    __syncthreads();

    // attention logits: e[n][f] = sum_c px[c]*aW[f,c] + sum_c pn[n][c]*aW[f,E+c] + ab[f]
    float epx = 0.f;
    float ea[N_];
    #pragma unroll
    for (int n = 0; n < N_; n++) ea[n] = 0.f;
    for (int c = 0; c < E_; c++) {
        float a1 = aWT[c*E_ + f];
        float a2 = aWT[(E_ + c)*E_ + f];
        epx += px[c] * a1;
        float pc0;
        #pragma unroll
        for (int n = 0; n < N_; n++) {
            pc0 = pn[n][c];
            ea[n] += pc0 * a2;
        }
    }
    float abf = ab[f];
    float mx = -1e30f;
    #pragma unroll
    for (int n = 0; n < N_; n++) {
        float ev = epx + ea[n] + abf;
        ev = (ev >= 0.f) ? ev : NEG * ev;    // LeakyReLU
        ea[n] = ev;
        mx = fmaxf(mx, ev);
    }
    float s = 0.f, o = 0.f;
    #pragma unroll
    for (int n = 0; n < N_; n++) {
        float p = expf(ea[n] - mx);
        s += p;
        o += p * pn[n][f];
    }
    outbuf[m*E_ + f] = o / s;
}

// ---------------- kernel 3: time-parallel LSTM preactivation ----------------
__global__ void pre_kernel(const int* __restrict__ x, const float* __restrict__ poi,
                           const float* __restrict__ Ub) {
    int m = blockIdx.x;
    int f = threadIdx.x;   // 0..127
    __shared__ float xs[3*E_];
    int ix = x[m];
    xs[f]        = poi[ix*E_ + f];
    xs[E_ + f]   = g_spatial[m*E_ + f];
    xs[2*E_ + f] = g_temporal[m*E_ + f];
    __syncthreads();
    float acc[4];
    #pragma unroll
    for (int k = 0; k < 4; k++) acc[k] = Ub[f + 128*k];
    for (int e = 0; e < E_; e++) {
        float xe = xs[e], se = xs[E_ + e], te = xs[2*E_ + e];
        #pragma unroll
        for (int k = 0; k < 4; k++) {
            int g = f + 128*k;
            acc[k] += xe*g_WT[e*G4_ + g] + se*g_sWT[e*G4_ + g] + te*g_tWT[e*G4_ + g];
        }
    }
    #pragma unroll
    for (int k = 0; k < 4; k++) g_preXST[m*G4_ + f + 128*k] = acc[k];
}

// ---------------- kernel 4: sequential LSTM (per-batch block) ----------------
__global__ void lstm_kernel() {
    int b = blockIdx.x;     // 0..31
    int j = threadIdx.x;    // 0..127
    __shared__ float hs[H_];
    hs[j] = 0.f;
    float c = 0.f;
    __syncthreads();
    const float4* UT4 = reinterpret_cast<const float4*>(g_UT4);
    for (int t = 0; t < T_; t++) {
        int m = b*T_ + t;
        float a0 = g_preXST[m*G4_ + j];
        float a1 = g_preXST[m*G4_ + 128 + j];
        float a2 = g_preXST[m*G4_ + 256 + j];
        float a3 = g_preXST[m*G4_ + 384 + j];
        #pragma unroll 8
        for (int e = 0; e < E_; e++) {
            float he = hs[e];
            float4 u = UT4[e*H_ + j];
            a0 += he*u.x; a1 += he*u.y; a2 += he*u.z; a3 += he*u.w;
        }
        float ig = 1.f / (1.f + expf(-a0));
        float fg = 1.f / (1.f + expf(-a1));
        float og = 1.f / (1.f + expf(-a2));
        float gg = tanhf(a3);
        c = fg*c + ig*gg;
        float h = og * tanhf(c);
        __syncthreads();
        hs[j] = h;
        g_hout[m*H_ + j] = h;
        __syncthreads();
    }
}

// ---------------- kernel 5: concat(user_emb, h) -> fused ----------------
__global__ void fuse_kernel(const int* __restrict__ users, const float* __restrict__ user_table) {
    int m = blockIdx.x;
    int k = threadIdx.x;   // 0..255
    int u = users[m];
    float v = (k < 128) ? user_table[u*128 + k] : g_hout[m*H_ + (k - 128)];
    g_fused[m*K_ + k] = v;
}

// ---------------- kernel 6: head GEMM logits = fused @ fuseW^T + b ----------------
// BM=128, BN=64, BK=8, 256 threads, 8x4 per-thread tile
#define BM 128
#define BN 64
#define BK 8
__global__ __launch_bounds__(256) void gemm_kernel(const float* __restrict__ Bw,
                                                   const float* __restrict__ bias,
                                                   float* __restrict__ Cout) {
    __shared__ float As[BK][BM];
    __shared__ float Bs[BK][BN];
    int tid = threadIdx.x;
    int n0 = blockIdx.x * BN;
    int m0 = blockIdx.y * BM;

    int tx = tid & 15;     // n dir
    int ty = tid >> 4;     // m dir
    float acc[8][4];
    #pragma unroll
    for (int i = 0; i < 8; i++)
        #pragma unroll
        for (int jj = 0; jj < 4; jj++) acc[i][jj] = 0.f;

    // A-load mapping: 256 threads, each one float4: row=tid>>1, c4=(tid&1)*4
    int arow = tid >> 1;
    int ac4  = (tid & 1) * 4;
    // B-load mapping: threads <128, one float4: n=tid>>1, c4=(tid&1)*4
    int brow = tid >> 1;
    int bc4  = (tid & 1) * 4;
    bool bload = (tid < 128);
    int gn = n0 + brow;

    for (int kb = 0; kb < K_; kb += BK) {
        float4 av = *reinterpret_cast<const float4*>(&g_fused[(m0 + arow)*K_ + kb + ac4]);
        As[ac4 + 0][arow] = av.x;
        As[ac4 + 1][arow] = av.y;
        As[ac4 + 2][arow] = av.z;
        As[ac4 + 3][arow] = av.w;
        if (bload) {
            float4 bv = make_float4(0.f, 0.f, 0.f, 0.f);
            if (gn < C_) bv = *reinterpret_cast<const float4*>(&Bw[(size_t)gn*K_ + kb + bc4]);
            Bs[bc4 + 0][brow] = bv.x;
            Bs[bc4 + 1][brow] = bv.y;
            Bs[bc4 + 2][brow] = bv.z;
            Bs[bc4 + 3][brow] = bv.w;
        }
        __syncthreads();
        #pragma unroll
        for (int k = 0; k < BK; k++) {
            float4 a0 = *reinterpret_cast<const float4*>(&As[k][ty*8]);
            float4 a1 = *reinterpret_cast<const float4*>(&As[k][ty*8 + 4]);
            float4 bv = *reinterpret_cast<const float4*>(&Bs[k][tx*4]);
            float a[8] = {a0.x,a0.y,a0.z,a0.w,a1.x,a1.y,a1.z,a1.w};
            float bb[4] = {bv.x,bv.y,bv.z,bv.w};
            #pragma unroll
            for (int i = 0; i < 8; i++)
                #pragma unroll
                for (int jj = 0; jj < 4; jj++)
                    acc[i][jj] += a[i] * bb[jj];
        }
        __syncthreads();
    }

    // epilogue with bias
    #pragma unroll
    for (int jj = 0; jj < 4; jj++) {
        int n = n0 + tx*4 + jj;
        if (n < C_) {
            float bsv = bias[n];
            #pragma unroll
            for (int i = 0; i < 8; i++) {
                int mm = m0 + ty*8 + i;
                Cout[(size_t)mm*C_ + n] = acc[i][jj] + bsv;
            }
        }
    }
}

// ---------------- launch ----------------
extern "C" void kernel_launch(void* const* d_in, const int* in_sizes, int n_in,
                              void* d_out, int out_size) {
    const int*   x       = (const int*)  d_in[0];
    const int*   users   = (const int*)  d_in[1];
    const int*   spn     = (const int*)  d_in[2];
    const int*   tpn     = (const int*)  d_in[3];
    const float* poi     = (const float*)d_in[4];
    const float* usert   = (const float*)d_in[5];
    const float* sp_w    = (const float*)d_in[6];
    const float* sp_aW   = (const float*)d_in[7];
    const float* sp_ab   = (const float*)d_in[8];
    const float* tp_w    = (const float*)d_in[9];
    const float* tp_aW   = (const float*)d_in[10];
    const float* tp_ab   = (const float*)d_in[11];
    const float* W       = (const float*)d_in[12];
    const float* U       = (const float*)d_in[13];
    const float* Ub      = (const float*)d_in[14];
    const float* sW      = (const float*)d_in[15];
    const float* tW      = (const float*)d_in[16];
    const float* fuseW   = (const float*)d_in[17];
    const float* fuseb   = (const float*)d_in[18];
    float* out = (float*)d_out;

    prep_kernel<<<256, 256>>>(sp_w, sp_aW, tp_w, tp_aW, W, U, sW, tW);
    gat_kernel<<<dim3(M_, 2), 128>>>(x, spn, tpn, poi, sp_ab, tp_ab);
    pre_kernel<<<M_, 128>>>(x, poi, Ub);
    lstm_kernel<<<B_, 128>>>();
    fuse_kernel<<<M_, 256>>>(users, usert);
    gemm_kernel<<<dim3((C_ + BN - 1)/BN, M_/BM), 256>>>(fuseW, fuseb, out);
}

// round 4
// speedup vs baseline: 1.8625x; 1.8625x over previous
#include <cuda_runtime.h>
#include <cuda_bf16.h>
#include <cstdint>

// Problem constants
#define B_  32
#define T_  64
#define M_  2048         // B*T
#define N_  16           // neighbors
#define E_  128
#define H_  128
#define G4_ 512          // 4*H
#define C_  100000
#define CP_ 100096       // padded rows = 782*128
#define K_  256          // UE + H
#define NEG 0.01f

// ---------------- scratch (device globals; no runtime alloc) ----------------
__device__ __align__(16) float g_spwT[E_*E_];       // [e][f]
__device__ __align__(16) float g_tpwT[E_*E_];
__device__ __align__(16) float g_spaWT[2*E_*E_];    // [c][f]
__device__ __align__(16) float g_tpaWT[2*E_*E_];
__device__ __align__(16) float g_WT [E_*G4_];       // [e][g]
__device__ __align__(16) float g_sWT[E_*G4_];
__device__ __align__(16) float g_tWT[E_*G4_];
__device__ __align__(16) float g_UT [E_*G4_];       // [e][g]
__device__ __align__(16) float g_spatial[M_*E_];
__device__ __align__(16) float g_temporal[M_*E_];
__device__ __align__(16) float g_preXST[M_*G4_];
__device__ __align__(16) float g_hout[M_*H_];
__device__ __align__(16) __nv_bfloat16 g_Ahi[M_*K_];
__device__ __align__(16) __nv_bfloat16 g_Alo[M_*K_];
__device__ __align__(16) __nv_bfloat16 g_Bhi[(size_t)CP_*K_];
__device__ __align__(16) __nv_bfloat16 g_Blo[(size_t)CP_*K_];

// ---------------- kernel 1: weight transposes ----------------
__global__ void prep_kernel(const float* __restrict__ sp_w, const float* __restrict__ sp_aW,
                            const float* __restrict__ tp_w, const float* __restrict__ tp_aW,
                            const float* __restrict__ W, const float* __restrict__ U,
                            const float* __restrict__ sW, const float* __restrict__ tW) {
    int i = blockIdx.x * blockDim.x + threadIdx.x;
    int stride = gridDim.x * blockDim.x;
    for (int j = i; j < E_*E_; j += stride) {
        int f = j >> 7, e = j & 127;
        g_spwT[e*E_ + f] = sp_w[j];
        g_tpwT[e*E_ + f] = tp_w[j];
    }
    for (int j = i; j < E_*2*E_; j += stride) {
        int f = j >> 8, c = j & 255;
        g_spaWT[c*E_ + f] = sp_aW[j];
        g_tpaWT[c*E_ + f] = tp_aW[j];
    }
    for (int j = i; j < G4_*E_; j += stride) {
        int g = j >> 7, e = j & 127;
        g_WT [e*G4_ + g] = W[j];
        g_sWT[e*G4_ + g] = sW[j];
        g_tWT[e*G4_ + g] = tW[j];
        g_UT [e*G4_ + g] = U[j];
    }
}

// ---------------- kernel 1b: split fuseW into bf16 hi/lo (padded) ----------------
__global__ void convB_kernel(const float* __restrict__ fw) {
    size_t p2 = (size_t)blockIdx.x * blockDim.x + threadIdx.x;
    size_t tot = (size_t)CP_ * K_ / 2;
    size_t stride = (size_t)gridDim.x * blockDim.x;
    for (; p2 < tot; p2 += stride) {
        size_t p = p2 * 2;
        size_t r = p >> 8;
        float2 v = make_float2(0.f, 0.f);
        if (r < C_) v = *reinterpret_cast<const float2*>(fw + p);
        __nv_bfloat16 h0 = __float2bfloat16(v.x);
        __nv_bfloat16 h1 = __float2bfloat16(v.y);
        float l0 = v.x - __bfloat162float(h0);
        float l1 = v.y - __bfloat162float(h1);
        __nv_bfloat162 hh; hh.x = h0; hh.y = h1;
        __nv_bfloat162 ll; ll.x = __float2bfloat16(l0); ll.y = __float2bfloat16(l1);
        reinterpret_cast<__nv_bfloat162*>(g_Bhi)[p2] = hh;
        reinterpret_cast<__nv_bfloat162*>(g_Blo)[p2] = ll;
    }
}

// ---------------- kernel 2: GAT (spatial + temporal) ----------------
__global__ void gat_kernel(const int* __restrict__ x,
                           const int* __restrict__ sp_neigh, const int* __restrict__ tp_neigh,
                           const float* __restrict__ poi,
                           const float* __restrict__ sp_ab, const float* __restrict__ tp_ab) {
    int m = blockIdx.x;
    int which = blockIdx.y;
    int f = threadIdx.x;
    const int*   neigh  = which ? tp_neigh : sp_neigh;
    const float* wT     = which ? g_tpwT   : g_spwT;
    const float* aWT    = which ? g_tpaWT  : g_spaWT;
    const float* ab     = which ? tp_ab    : sp_ab;
    float*       outbuf = which ? g_temporal : g_spatial;

    __shared__ float nb[17][E_];
    __shared__ float px[E_];
    __shared__ float pn[N_][E_];

    {
        int ix = x[m];
        nb[16][f] = poi[ix*E_ + f];
        #pragma unroll
        for (int n = 0; n < N_; n++) {
            int idx = neigh[m*N_ + n];
            nb[n][f] = poi[idx*E_ + f];
        }
    }
    __syncthreads();

    float accx = 0.f;
    float accn[N_];
    #pragma unroll
    for (int n = 0; n < N_; n++) accn[n] = 0.f;
    for (int e = 0; e < E_; e++) {
        float wv = wT[e*E_ + f];
        accx += nb[16][e] * wv;
        #pragma unroll
        for (int n = 0; n < N_; n++) accn[n] += nb[n][e] * wv;
    }
    px[f] = accx;
    #pragma unroll
    for (int n = 0; n < N_; n++) pn[n][f] = accn[n];
    __syncthreads();

    float epx = 0.f;
    float ea[N_];
    #pragma unroll
    for (int n = 0; n < N_; n++) ea[n] = 0.f;
    for (int c = 0; c < E_; c++) {
        float a1 = aWT[c*E_ + f];
        float a2 = aWT[(E_ + c)*E_ + f];
        epx += px[c] * a1;
        #pragma unroll
        for (int n = 0; n < N_; n++) ea[n] += pn[n][c] * a2;
    }
    float abf = ab[f];
    float mx = -1e30f;
    #pragma unroll
    for (int n = 0; n < N_; n++) {
        float ev = epx + ea[n] + abf;
        ev = (ev >= 0.f) ? ev : NEG * ev;
        ea[n] = ev;
        mx = fmaxf(mx, ev);
    }
    float s = 0.f, o = 0.f;
    #pragma unroll
    for (int n = 0; n < N_; n++) {
        float p = expf(ea[n] - mx);
        s += p;
        o += p * pn[n][f];
    }
    outbuf[m*E_ + f] = o / s;
}

// ---------------- kernel 3: LSTM preactivation, 16 rows per block ----------------
__global__ __launch_bounds__(512) void pre_kernel(const int* __restrict__ x,
                                                  const float* __restrict__ poi,
                                                  const float* __restrict__ Ub) {
    int tid = threadIdx.x;
    int m0 = blockIdx.x * 16;
    __shared__ float xs[16][3*E_];
    for (int i = tid; i < 16*3*E_; i += 512) {
        int r = i / (3*E_), e = i % (3*E_);
        int m = m0 + r;
        float v;
        if (e < E_)        v = poi[x[m]*E_ + e];
        else if (e < 2*E_) v = g_spatial[m*E_ + (e - E_)];
        else               v = g_temporal[m*E_ + (e - 2*E_)];
        xs[r][e] = v;
    }
    __syncthreads();
    float ub = Ub[tid];
    float acc[16];
    #pragma unroll
    for (int r = 0; r < 16; r++) acc[r] = ub;
    for (int e = 0; e < E_; e++) {
        float w1 = g_WT [e*G4_ + tid];
        float w2 = g_sWT[e*G4_ + tid];
        float w3 = g_tWT[e*G4_ + tid];
        #pragma unroll
        for (int r = 0; r < 16; r++)
            acc[r] += xs[r][e]*w1 + xs[r][e + E_]*w2 + xs[r][e + 2*E_]*w3;
    }
    #pragma unroll
    for (int r = 0; r < 16; r++)
        g_preXST[(size_t)(m0 + r)*G4_ + tid] = acc[r];
}

// ---------------- kernel 4: sequential LSTM, 512 threads ----------------
__global__ __launch_bounds__(512) void lstm_kernel() {
    int b = blockIdx.x;
    int tid = threadIdx.x;
    int g = tid >> 7, j = tid & 127;
    __shared__ float hs[H_];
    __shared__ float gsm[4][H_];
    float c = 0.f;
    if (tid < H_) hs[tid] = 0.f;
    __syncthreads();
    for (int t = 0; t < T_; t++) {
        int m = b*T_ + t;
        float acc = g_preXST[(size_t)m*G4_ + tid];
        #pragma unroll 8
        for (int e = 0; e < E_; e++)
            acc += hs[e] * g_UT[e*G4_ + tid];
        gsm[g][j] = acc;
        __syncthreads();
        if (g == 0) {
            float ig = 1.f / (1.f + expf(-gsm[0][j]));
            float fg = 1.f / (1.f + expf(-gsm[1][j]));
            float og = 1.f / (1.f + expf(-gsm[2][j]));
            float gg = tanhf(gsm[3][j]);
            c = fg*c + ig*gg;
            float h = og * tanhf(c);
            hs[j] = h;
            g_hout[m*H_ + j] = h;
        }
        __syncthreads();
    }
}

// ---------------- kernel 5: concat + bf16 hi/lo split of A ----------------
__global__ void fuse_kernel(const int* __restrict__ users, const float* __restrict__ user_table) {
    int m = blockIdx.x;
    int k = threadIdx.x;
    int u = users[m];
    float v = (k < 128) ? user_table[u*128 + k] : g_hout[m*H_ + (k - 128)];
    __nv_bfloat16 hi = __float2bfloat16(v);
    float lo = v - __bfloat162float(hi);
    g_Ahi[m*K_ + k] = hi;
    g_Alo[m*K_ + k] = __float2bfloat16(lo);
}

// ---------------- kernel 6: head GEMM via mma.sync (HMMA bf16, fp32 accum) ------
// CTA tile 128x128, 8 warps (2x4), warp tile 64x32, BK=32, double-buffered cp.async.
// K loop flattened over 3 passes: Ahi*Bhi, Ahi*Blo, Alo*Bhi  (24 chunks of 32).
#define ROWB 40              // padded smem row stride in bf16 (80 bytes)
#define NKCH 24

__device__ __forceinline__ void cpa16s(uint32_t dst, const void* src) {
    asm volatile("cp.async.cg.shared.global [%0], [%1], 16;" :: "r"(dst), "l"(src));
}
__device__ __forceinline__ void ldsm4(uint32_t* r, uint32_t addr) {
    asm volatile("ldmatrix.sync.aligned.m8n8.x4.shared.b16 {%0,%1,%2,%3}, [%4];"
                 : "=r"(r[0]), "=r"(r[1]), "=r"(r[2]), "=r"(r[3]) : "r"(addr));
}
__device__ __forceinline__ void mma16816(float* c, const uint32_t* a, uint32_t b0, uint32_t b1) {
    asm volatile("mma.sync.aligned.m16n8k16.row.col.f32.bf16.bf16.f32 "
                 "{%0,%1,%2,%3}, {%4,%5,%6,%7}, {%8,%9}, {%0,%1,%2,%3};"
                 : "+f"(c[0]), "+f"(c[1]), "+f"(c[2]), "+f"(c[3])
                 : "r"(a[0]), "r"(a[1]), "r"(a[2]), "r"(a[3]), "r"(b0), "r"(b1));
}

__global__ __launch_bounds__(256) void gemm_mma_kernel(const float* __restrict__ bias,
                                                       float* __restrict__ out) {
    __shared__ __align__(16) __nv_bfloat16 sA[2][128*ROWB];
    __shared__ __align__(16) __nv_bfloat16 sB[2][128*ROWB];
    int tid = threadIdx.x;
    int wid = tid >> 5, lane = tid & 31;
    int wm = wid >> 2, wn = wid & 3;
    int m0 = blockIdx.x * 128;
    int n0 = blockIdx.y * 128;

    float acc[16][4];
    #pragma unroll
    for (int i = 0; i < 16; i++)
        #pragma unroll
        for (int q = 0; q < 4; q++) acc[i][q] = 0.f;

    uint32_t sA_u[2], sB_u[2];
    sA_u[0] = (uint32_t)__cvta_generic_to_shared(sA[0]);
    sA_u[1] = (uint32_t)__cvta_generic_to_shared(sA[1]);
    sB_u[0] = (uint32_t)__cvta_generic_to_shared(sB[0]);
    sB_u[1] = (uint32_t)__cvta_generic_to_shared(sB[1]);

    // loader: 512 16B-granules each for A and B; 256 threads x 2 each
    auto load_chunk = [&](int kc, int stg) {
        int pass = kc >> 3;
        int ko = (kc & 7) * 32;
        const __nv_bfloat16* Ag = (pass == 2) ? g_Alo : g_Ahi;
        const __nv_bfloat16* Bg = (pass == 1) ? g_Blo : g_Bhi;
        #pragma unroll
        for (int it = 0; it < 2; it++) {
            int i = tid + it*256;          // 0..511
            int r = i >> 2, gc = i & 3;    // row, 16B granule (8 bf16)
            uint32_t soff = (uint32_t)(r*ROWB + gc*8) * 2u;
            cpa16s(sA_u[stg] + soff, Ag + (size_t)(m0 + r)*K_ + ko + gc*8);
            cpa16s(sB_u[stg] + soff, Bg + (size_t)(n0 + r)*K_ + ko + gc*8);
        }
        asm volatile("cp.async.commit_group;" ::: "memory");
    };

    load_chunk(0, 0);

    int rowsel = lane & 7;
    int mat01 = (lane >> 3) & 1;   // +8 rows for odd matrices
    int mat23 = (lane >> 4);       // +8 cols for matrices 2,3

    for (int kc = 0; kc < NKCH; kc++) {
        int stg = kc & 1;
        if (kc + 1 < NKCH) {
            load_chunk(kc + 1, (kc + 1) & 1);
            asm volatile("cp.async.wait_group 1;" ::: "memory");
        } else {
            asm volatile("cp.async.wait_group 0;" ::: "memory");
        }
        __syncthreads();

        #pragma unroll
        for (int s = 0; s < 2; s++) {
            int colb = s*16 + mat23*8;
            uint32_t afr[4][4];
            #pragma unroll
            for (int im = 0; im < 4; im++) {
                int row = wm*64 + im*16 + mat01*8 + rowsel;
                ldsm4(afr[im], sA_u[stg] + (uint32_t)(row*ROWB + colb)*2u);
            }
            uint32_t bfr[2][4];
            #pragma unroll
            for (int j2 = 0; j2 < 2; j2++) {
                int row = wn*32 + j2*16 + mat01*8 + rowsel;
                ldsm4(bfr[j2], sB_u[stg] + (uint32_t)(row*ROWB + colb)*2u);
            }
            #pragma unroll
            for (int im = 0; im < 4; im++) {
                #pragma unroll
                for (int jn = 0; jn < 4; jn++) {
                    int h = jn & 1;
                    mma16816(acc[im*4 + jn], afr[im], bfr[jn>>1][h], bfr[jn>>1][h + 2]);
                }
            }
        }
        __syncthreads();
    }

    // epilogue: c0=(g,2t) c1=(g,2t+1) c2=(g+8,2t) c3=(g+8,2t+1)
    int g = lane >> 2, t = lane & 3;
    #pragma unroll
    for (int im = 0; im < 4; im++) {
        int row = m0 + wm*64 + im*16 + g;
        size_t r0 = (size_t)row * C_;
        #pragma unroll
        for (int jn = 0; jn < 4; jn++) {
            int col = n0 + wn*32 + jn*8 + 2*t;
            if (col < C_) {
                float2 bv = *reinterpret_cast<const float2*>(bias + col);
                const float* a = acc[im*4 + jn];
                float2 v0 = make_float2(a[0] + bv.x, a[1] + bv.y);
                float2 v1 = make_float2(a[2] + bv.x, a[3] + bv.y);
                *reinterpret_cast<float2*>(out + r0 + col) = v0;
                *reinterpret_cast<float2*>(out + r0 + (size_t)8*C_ + col) = v1;
            }
        }
    }
}

// ---------------- launch ----------------
extern "C" void kernel_launch(void* const* d_in, const int* in_sizes, int n_in,
                              void* d_out, int out_size) {
    const int*   x       = (const int*)  d_in[0];
    const int*   users   = (const int*)  d_in[1];
    const int*   spn     = (const int*)  d_in[2];
    const int*   tpn     = (const int*)  d_in[3];
    const float* poi     = (const float*)d_in[4];
    const float* usert   = (const float*)d_in[5];
    const float* sp_w    = (const float*)d_in[6];
    const float* sp_aW   = (const float*)d_in[7];
    const float* sp_ab   = (const float*)d_in[8];
    const float* tp_w    = (const float*)d_in[9];
    const float* tp_aW   = (const float*)d_in[10];
    const float* tp_ab   = (const float*)d_in[11];
    const float* W       = (const float*)d_in[12];
    const float* U       = (const float*)d_in[13];
    const float* Ub      = (const float*)d_in[14];
    const float* sW      = (const float*)d_in[15];
    const float* tW      = (const float*)d_in[16];
    const float* fuseW   = (const float*)d_in[17];
    const float* fuseb   = (const float*)d_in[18];
    float* out = (float*)d_out;

    prep_kernel<<<256, 256>>>(sp_w, sp_aW, tp_w, tp_aW, W, U, sW, tW);
    convB_kernel<<<8192, 256>>>(fuseW);
    gat_kernel<<<dim3(M_, 2), 128>>>(x, spn, tpn, poi, sp_ab, tp_ab);
    pre_kernel<<<M_/16, 512>>>(x, poi, Ub);
    lstm_kernel<<<B_, 512>>>();
    fuse_kernel<<<M_, 256>>>(users, usert);
    gemm_mma_kernel<<<dim3(M_/128, CP_/128), 256>>>(fuseb, out);
}